// round 14
// baseline (speedup 1.0000x reference)
#include <cuda_runtime.h>
#include <cuda_fp16.h>
#include <cstdint>
#include <math.h>

// ---------------- problem constants ----------------
#define BB 4
#define LL 2048
#define DD 2048
#define RR 2048
#define DHH 512
#define MM (BB * LL)          // 8192
#define NCH 16
#define CHL (LL / NCH)        // 128

// ---------------- device scratch ----------------
__device__ __half g_xhi[(size_t)MM * DD];
__device__ __half g_wuhi[(size_t)RR * DD];
__device__ __half g_wvhi[(size_t)RR * DD];
__device__ __half g_wg1hi[(size_t)DHH * DD];
__device__ __half g_wg2hi[(size_t)RR * DHH];
__device__ __half g_hhi[(size_t)MM * DHH];
__device__ __half g_ghi[(size_t)MM * RR];
__device__ float g_u[(size_t)MM * RR];
__device__ float g_v[(size_t)MM * RR];
__device__ float g_g[(size_t)MM * RR];
__device__ float g_part[(size_t)BB * NCH * RR];

// ---------------- PTX helpers (arch-agnostic only) ----------------
__device__ __forceinline__ uint32_t smem_u32(const void* p) {
    uint32_t a;
    asm("{ .reg .u64 t; cvta.to.shared.u64 t, %1; cvt.u32.u64 %0, t; }" : "=r"(a) : "l"(p));
    return a;
}
__device__ __forceinline__ void cp16(uint32_t dst, const void* src) {
    asm volatile("cp.async.cg.shared.global [%0], [%1], 16;" :: "r"(dst), "l"(src));
}
#define CP_COMMIT() asm volatile("cp.async.commit_group;" ::: "memory")
#define CP_WAIT(n)  asm volatile("cp.async.wait_group %0;" :: "n"(n) : "memory")

#define LDSM4(r, addr) \
    asm volatile("ldmatrix.sync.aligned.m8n8.x4.shared.b16 {%0,%1,%2,%3}, [%4];" \
        : "=r"((r)[0]), "=r"((r)[1]), "=r"((r)[2]), "=r"((r)[3]) : "r"(addr))

__device__ __forceinline__ void mma16816(float* c, const uint32_t* a, uint32_t b0, uint32_t b1) {
    asm volatile(
        "mma.sync.aligned.m16n8k16.row.col.f32.f16.f16.f32 "
        "{%0,%1,%2,%3}, {%4,%5,%6,%7}, {%8,%9}, {%0,%1,%2,%3};"
        : "+f"(c[0]), "+f"(c[1]), "+f"(c[2]), "+f"(c[3])
        : "r"(a[0]), "r"(a[1]), "r"(a[2]), "r"(a[3]), "r"(b0), "r"(b1));
}

// swizzle for rows of NKC*128 bytes: 16B-chunk c in 0..8*NKC-1.
// Each 128B half keeps the SW128 pattern; conflict-free per ldmatrix phase.
template <int NKC>
__device__ __forceinline__ uint32_t swz(int r, int c) {
    return (uint32_t)(r * (128 * NKC) + ((c >> 3) << 7) + ((((c & 7) ^ (r & 7))) << 4));
}

// load one (64*NKC)-K chunk's tiles into a stage. Layout: [A] [B]
template <int TBM_, int TBNP, int NKC, int A_TILE_>
__device__ __forceinline__ void load_ab(uint32_t st,
                                        const __half* __restrict__ Ahi,
                                        const __half* __restrict__ Bhi,
                                        int K, int row0, int col0, int k0, int tid) {
    constexpr int NCH_S = 8 * NKC;   // 16B chunks per row
#pragma unroll
    for (int i = 0; i < TBM_ * NCH_S / 256; i++) {
        int id = tid + i * 256;
        int r = id / NCH_S, c = id % NCH_S;
        size_t srcoff = (size_t)(row0 + r) * K + k0 + c * 8;
        cp16(st + swz<NKC>(r, c), Ahi + srcoff);
    }
#pragma unroll
    for (int i = 0; i < TBNP * NCH_S / 256; i++) {
        int id = tid + i * 256;
        int r = id / NCH_S, c = id % NCH_S;
        size_t srcoff = (size_t)(col0 + r) * K + k0 + c * 8;
        cp16(st + A_TILE_ + swz<NKC>(r, c), Bhi + srcoff);
    }
}

// ---------------------------------------------------------------------------
// fp16 warp-MMA GEMM: C[m,n] = sum_k A[m,k]*B[n,k]   (single pass)
// DUAL: blockIdx.z selects (B,bias,C)
// NWN: warps along n ; TBNP: CTA n-tile ; NKC: 64-K chunks per stage
// MINB: min blocks/SM ; NST: pipeline stages
// EPI 0: C = z + bias
// EPI 1: relu(z + bias) -> fp16 (Ohi)
// EPI 2: g = sigmoid(z + bias); write gbuf; part = chunk sums of u*g
// EPI 3: C = depthwise_conv3(x) + z
// ---------------------------------------------------------------------------
template <int EPI, bool DUAL, int NWN, int MINB, int NST, int NKC, int TBNP>
__global__ __launch_bounds__(256, MINB)
void bsgemm(const __half* __restrict__ Ahi,
            const __half* __restrict__ Bhi_,
            const float* __restrict__ bias_,
            float* __restrict__ C_,
            __half* __restrict__ Ohi,
            const __half* __restrict__ Bhi2,
            const float* __restrict__ bias2, float* __restrict__ Cd2,
            const float* __restrict__ cw, const float* __restrict__ cb,
            const float* __restrict__ xp,
            float* __restrict__ gbuf, float* __restrict__ part,
            int M, int N, int K) {
    constexpr int TBM_    = 64 * (8 / NWN);
    constexpr int A_TILE_ = TBM_ * 128 * NKC;
    constexpr int B_TILE_ = TBNP * 128 * NKC;
    constexpr int STAGE_  = A_TILE_ + B_TILE_;
    constexpr int WNT     = TBNP / NWN;   // warp n-tile
    constexpr int NJ      = WNT / 8;
    constexpr int PB      = NJ / 2;

    extern __shared__ __align__(128) char smem[];
    const uint32_t sb = smem_u32(smem);
    const int tid  = threadIdx.x;
    const int wid  = tid >> 5;
    const int lane = tid & 31;
    const int wm = wid / NWN;
    const int wn = wid % NWN;
    const int row0 = blockIdx.y * TBM_;
    const int col0 = blockIdx.x * TBNP;
    const int nchunks = K / (64 * NKC);

    const __half* Bhi = Bhi_;
    const float* bias = bias_;
    float* C = C_;
    if (DUAL && blockIdx.z == 1) { Bhi = Bhi2; bias = bias2; C = Cd2; }

    // ldmatrix lane mapping
    const int lr = lane & 7;
    const int j  = lane >> 3;
    const int arow  = ((j & 1) << 3) + lr;
    const int acsel = j >> 1;
    const int brow  = ((j >> 1) << 3) + lr;
    const int bcsel = j & 1;

    float acc[4][NJ][4];
#pragma unroll
    for (int mi = 0; mi < 4; mi++)
#pragma unroll
        for (int nj = 0; nj < NJ; nj++)
#pragma unroll
            for (int q = 0; q < 4; q++) acc[mi][nj][q] = 0.0f;

    // prologue: chunks 0..NST-2
#pragma unroll
    for (int p = 0; p < NST - 1; p++) {
        load_ab<TBM_, TBNP, NKC, A_TILE_>(sb + p * STAGE_, Ahi, Bhi,
                                          K, row0, col0, p * 64 * NKC, tid);
        CP_COMMIT();
    }

    for (int c = 0; c < nchunks; c++) {
        if (c == nchunks - 1) CP_WAIT(0); else CP_WAIT(NST - 2);
        __syncthreads();

        const int nxt = c + NST - 1;
        if (nxt < nchunks) {
            load_ab<TBM_, TBNP, NKC, A_TILE_>(sb + (nxt % NST) * STAGE_, Ahi, Bhi,
                                              K, row0, col0, nxt * 64 * NKC, tid);
            CP_COMMIT();
        }

        const uint32_t sA = sb + (c % NST) * STAGE_;
        const uint32_t sB = sA + A_TILE_;

#pragma unroll
        for (int s = 0; s < 4 * NKC; s++) {
            uint32_t ah[4][4], bh[PB][4];
#pragma unroll
            for (int mi = 0; mi < 4; mi++) {
                int r = wm * 64 + mi * 16 + arow;
                LDSM4(ah[mi], sA + swz<NKC>(r, 2 * s + acsel));
            }
#pragma unroll
            for (int p = 0; p < PB; p++) {
                int r = wn * WNT + p * 16 + brow;
                LDSM4(bh[p], sB + swz<NKC>(r, 2 * s + bcsel));
            }
#pragma unroll
            for (int mi = 0; mi < 4; mi++)
#pragma unroll
                for (int nj = 0; nj < NJ; nj++)
                    mma16816(acc[mi][nj], ah[mi], bh[nj >> 1][(nj & 1) * 2], bh[nj >> 1][(nj & 1) * 2 + 1]);
        }
    }

    // -------- epilogue --------
    const int g_ = lane >> 2, t = lane & 3;
    float psum[NJ][2];
    if (EPI == 2) {
#pragma unroll
        for (int nj = 0; nj < NJ; nj++) { psum[nj][0] = 0.0f; psum[nj][1] = 0.0f; }
    }
#pragma unroll
    for (int mi = 0; mi < 4; mi++) {
#pragma unroll
        for (int nj = 0; nj < NJ; nj++) {
            int row = row0 + wm * 64 + mi * 16 + g_;
            int col = col0 + wn * WNT + nj * 8 + 2 * t;
            size_t i0 = (size_t)row * N + col;
            size_t i1 = (size_t)(row + 8) * N + col;
            float* z = acc[mi][nj];
            if (EPI == 0) {
                float b0 = bias[col], b1 = bias[col + 1];
                *(float2*)(C + i0) = make_float2(z[0] + b0, z[1] + b1);
                *(float2*)(C + i1) = make_float2(z[2] + b0, z[3] + b1);
            } else if (EPI == 1) {
                float b0 = bias[col], b1 = bias[col + 1];
                float v0 = fmaxf(z[0] + b0, 0.0f), v1 = fmaxf(z[1] + b1, 0.0f);
                float v2 = fmaxf(z[2] + b0, 0.0f), v3 = fmaxf(z[3] + b1, 0.0f);
                *(__half2*)(Ohi + i0) = __halves2half2(__float2half(v0), __float2half(v1));
                *(__half2*)(Ohi + i1) = __halves2half2(__float2half(v2), __float2half(v3));
            } else if (EPI == 2) {
                float b0 = bias[col], b1 = bias[col + 1];
                float g0 = 1.0f / (1.0f + __expf(-(z[0] + b0)));
                float g1 = 1.0f / (1.0f + __expf(-(z[1] + b1)));
                float g2 = 1.0f / (1.0f + __expf(-(z[2] + b0)));
                float g3 = 1.0f / (1.0f + __expf(-(z[3] + b1)));
                float2 u0 = *(float2*)(C + i0), u1 = *(float2*)(C + i1);
                *(float2*)(gbuf + i0) = make_float2(g0, g1);
                *(float2*)(gbuf + i1) = make_float2(g2, g3);
                psum[nj][0] += u0.x * g0 + u1.x * g2;
                psum[nj][1] += u0.y * g1 + u1.y * g3;
            } else {  // EPI == 3: out = conv3(x) + z
                int l0 = row & (LL - 1);
                int l1 = l0 + 8;
                float w0a = cw[3 * col + 0], w1a = cw[3 * col + 1], w2a = cw[3 * col + 2];
                float w0b = cw[3 * col + 3], w1b = cw[3 * col + 4], w2b = cw[3 * col + 5];
                float cb0 = cb[col], cb1 = cb[col + 1];
                const float* xr0 = xp + i0;
                const float* xr1 = xp + i1;
                float2 xc0 = *(const float2*)xr0;
                float2 xc1 = *(const float2*)xr1;
                float2 xq0 = *(const float2*)(xr0 + N);
                float2 xm1 = *(const float2*)(xr1 - N);
                float2 xm0 = (l0 > 0)      ? *(const float2*)(xr0 - N) : make_float2(0.f, 0.f);
                float2 xq1 = (l1 < LL - 1) ? *(const float2*)(xr1 + N) : make_float2(0.f, 0.f);
                float o0 = cb0 + w1a * xc0.x + w2a * xq0.x + z[0] + (l0 > 0 ? w0a * xm0.x : 0.f);
                float o1 = cb1 + w1b * xc0.y + w2b * xq0.y + z[1] + (l0 > 0 ? w0b * xm0.y : 0.f);
                float o2 = cb0 + w1a * xc1.x + w0a * xm1.x + z[2] + (l1 < LL - 1 ? w2a * xq1.x : 0.f);
                float o3 = cb1 + w1b * xc1.y + w0b * xm1.y + z[3] + (l1 < LL - 1 ? w2b * xq1.y : 0.f);
                *(float2*)(C + i0) = make_float2(o0, o1);
                *(float2*)(C + i1) = make_float2(o2, o3);
            }
        }
    }

    if (EPI == 2) {   // gates path: NWN=4, TBNP=128, TBM_=128
#pragma unroll
        for (int nj = 0; nj < NJ; nj++) {
#pragma unroll
            for (int k = 0; k < 2; k++) {
                float v = psum[nj][k];
                v += __shfl_xor_sync(0xffffffffu, v, 4);
                v += __shfl_xor_sync(0xffffffffu, v, 8);
                v += __shfl_xor_sync(0xffffffffu, v, 16);
                psum[nj][k] = v;
            }
        }
        __syncthreads();
        float* red = (float*)smem;       // [NWM wm][128 cols]
        if (lane < 4) {
#pragma unroll
            for (int nj = 0; nj < NJ; nj++) {
                red[wm * 128 + wn * WNT + nj * 8 + 2 * lane + 0] = psum[nj][0];
                red[wm * 128 + wn * WNT + nj * 8 + 2 * lane + 1] = psum[nj][1];
            }
        }
        __syncthreads();
        {
            int ch = tid >> 7, cl = tid & 127;   // chunk-within-CTA, column
            if (ch < TBM_ / 128) {
                float s = red[(2 * ch) * 128 + cl] + red[(2 * ch + 1) * 128 + cl];
                int bidx = row0 >> 11;
                int cbase = (row0 & (LL - 1)) >> 7;
                part[((size_t)bidx * NCH + cbase + ch) * (size_t)N + col0 + cl] = s;
            }
        }
    }
}

// ---------------------------------------------------------------------------
// elementwise kernels
// ---------------------------------------------------------------------------
__device__ __forceinline__ uint32_t pack_h(float a, float b) {
    __half2 h = __halves2half2(__float2half(a), __float2half(b));
    return *(uint32_t*)&h;
}

__global__ void split_kernel(const float* __restrict__ s, __half* __restrict__ hi, size_t n) {
    size_t i = ((size_t)blockIdx.x * blockDim.x + threadIdx.x) * 8;
    if (i >= n) return;
    float4 a = *(const float4*)(s + i);
    float4 b = *(const float4*)(s + i + 4);
    uint4 h;
    h.x = pack_h(a.x, a.y); h.y = pack_h(a.z, a.w);
    h.z = pack_h(b.x, b.y); h.w = pack_h(b.z, b.w);
    *(uint4*)(hi + i) = h;
}

__global__ void scanB_kernel(float* __restrict__ part) {
    int tid = blockIdx.x * blockDim.x + threadIdx.x;
    if (tid >= BB * RR) return;
    int r = tid % RR;
    int b = tid / RR;
    float run = 0.0f;
    for (int c = 0; c < NCH; c++) {
        size_t idx = ((size_t)b * NCH + c) * RR + r;
        float t = part[idx];
        part[idx] = run;
        run += t;
    }
}

__global__ void scanC_kernel(const float* __restrict__ u, const float* __restrict__ v,
                             const float* __restrict__ g, const float* __restrict__ part,
                             __half* __restrict__ ghi) {
    int tid = blockIdx.x * blockDim.x + threadIdx.x;
    if (tid >= BB * NCH * RR) return;
    int r = tid % RR;
    int c = (tid / RR) % NCH;
    int b = tid / (RR * NCH);
    float acc = part[((size_t)b * NCH + c) * RR + r];
    size_t base = ((size_t)b * LL + c * CHL) * RR + r;
    for (int l = 0; l < CHL; l++) {
        size_t idx = base + (size_t)l * RR;
        float gg = g[idx];
        acc += u[idx] * gg;
        ghi[idx] = __float2half(acc * (v[idx] * gg));
    }
}

// ---------------------------------------------------------------------------
extern "C" void kernel_launch(void* const* d_in, const int* in_sizes, int n_in,
                              void* d_out, int out_size) {
    const float* x      = (const float*)d_in[0];
    const float* Wu     = (const float*)d_in[1];
    const float* bu     = (const float*)d_in[2];
    const float* Wv     = (const float*)d_in[3];
    const float* bv     = (const float*)d_in[4];
    const float* Wg1    = (const float*)d_in[5];
    const float* bg1    = (const float*)d_in[6];
    const float* Wg2    = (const float*)d_in[7];
    const float* bg2    = (const float*)d_in[8];
    const float* conv_w = (const float*)d_in[9];
    const float* conv_b = (const float*)d_in[10];
    float* out = (float*)d_out;

    __half *xhi, *wuhi, *wvhi, *wg1hi, *wg2hi, *hhi, *ghi;
    float *pu, *pv, *pg, *ppart;
    cudaGetSymbolAddress((void**)&xhi, g_xhi);
    cudaGetSymbolAddress((void**)&wuhi, g_wuhi);
    cudaGetSymbolAddress((void**)&wvhi, g_wvhi);
    cudaGetSymbolAddress((void**)&wg1hi, g_wg1hi);
    cudaGetSymbolAddress((void**)&wg2hi, g_wg2hi);
    cudaGetSymbolAddress((void**)&hhi, g_hhi);
    cudaGetSymbolAddress((void**)&ghi, g_ghi);
    cudaGetSymbolAddress((void**)&pu, g_u);        cudaGetSymbolAddress((void**)&pv, g_v);
    cudaGetSymbolAddress((void**)&pg, g_g);        cudaGetSymbolAddress((void**)&ppart, g_part);

    // dual / uv: NWN=4, TBN=64, NKC=2 (TBK=128), NST=2 -> 2*48KB = 98304, 2 CTAs/SM
    cudaFuncSetAttribute(bsgemm<0,true,4,2,2,2,64>,   cudaFuncAttributeMaxDynamicSharedMemorySize, 98304);
    cudaFuncSetAttribute(bsgemm<3,false,4,2,2,2,64>,  cudaFuncAttributeMaxDynamicSharedMemorySize, 98304);
    // h: NWN=2, TBN=128, NKC=1, NST=2 -> 2*48KB
    cudaFuncSetAttribute(bsgemm<1,false,2,1,2,1,128>, cudaFuncAttributeMaxDynamicSharedMemorySize, 98304);
    // gates: NWN=4, TBN=128, NKC=1, NST=2 -> 2*32KB, 2 CTAs/SM
    cudaFuncSetAttribute(bsgemm<2,false,4,2,2,1,128>, cudaFuncAttributeMaxDynamicSharedMemorySize, 65536);

    // fp16 conversions
    split_kernel<<<(unsigned)((size_t)MM * DD / 8 / 256), 256>>>(x, xhi, (size_t)MM * DD);
    split_kernel<<<(unsigned)((size_t)RR * DD / 8 / 256), 256>>>(Wu, wuhi, (size_t)RR * DD);
    split_kernel<<<(unsigned)((size_t)RR * DD / 8 / 256), 256>>>(Wv, wvhi, (size_t)RR * DD);

    // dual u/v GEMM (1-pass fp16, TBK=128): z=0 -> u, z=1 -> v
    bsgemm<0,true,4,2,2,2,64><<<dim3(RR / 64, MM / 128, 2), 256, 98304>>>(
        xhi, wuhi, bu, pu, nullptr,
        wvhi, bv, pv,
        nullptr, nullptr, nullptr, nullptr, nullptr, MM, RR, DD);

    // gate path (plain fp16)
    split_kernel<<<(unsigned)((size_t)DHH * DD / 8 / 256), 256>>>(Wg1, wg1hi, (size_t)DHH * DD);
    split_kernel<<<(unsigned)((size_t)RR * DHH / 8 / 256), 256>>>(Wg2, wg2hi, (size_t)RR * DHH);
    // h = relu(x Wg1^T + bg1) -> fp16
    bsgemm<1,false,2,1,2,1,128><<<dim3(DHH / 128, MM / 256), 256, 98304>>>(
        xhi, wg1hi, bg1, nullptr, hhi,
        nullptr, nullptr, nullptr,
        nullptr, nullptr, nullptr, nullptr, nullptr, MM, DHH, DD);
    // gates: write g, fused chunk partial sums of u*g -> part
    bsgemm<2,false,4,2,2,1,128><<<dim3(RR / 128, MM / 128), 256, 65536>>>(
        hhi, wg2hi, bg2, pu, nullptr,
        nullptr, nullptr, nullptr,
        nullptr, nullptr, nullptr, pg, ppart, MM, RR, DHH);

    // exclusive prefix over chunks, then apply gates + cumsum + multiply -> fp16
    scanB_kernel<<<(BB * RR + 255) / 256, 256>>>(ppart);
    scanC_kernel<<<(BB * NCH * RR + 255) / 256, 256>>>(pu, pv, pg, ppart, ghi);

    // out = conv3(x) + global_out @ Wu   (1-pass fp16, TBK=128)
    bsgemm<3,false,4,2,2,2,64><<<dim3(DD / 64, MM / 128), 256, 98304>>>(
        ghi, wuhi, nullptr, out, nullptr,
        nullptr, nullptr, nullptr,
        conv_w, conv_b, x, nullptr, nullptr, MM, DD, RR);
}

// round 15
// speedup vs baseline: 1.1278x; 1.1278x over previous
#include <cuda_runtime.h>
#include <cuda_fp16.h>
#include <cstdint>
#include <math.h>

// ---------------- problem constants ----------------
#define BB 4
#define LL 2048
#define DD 2048
#define RR 2048
#define DHH 512
#define MM (BB * LL)          // 8192
#define NCH 16
#define CHL (LL / NCH)        // 128

#define TBK 64
#define B_TILE 16384          // 128 rows * 128B

// ---------------- device scratch ----------------
__device__ __half g_xhi[(size_t)MM * DD];
__device__ __half g_wuhi[(size_t)RR * DD];
__device__ __half g_wvhi[(size_t)RR * DD];
__device__ __half g_wg1hi[(size_t)DHH * DD];
__device__ __half g_wg2hi[(size_t)RR * DHH];
__device__ __half g_hhi[(size_t)MM * DHH];
__device__ __half g_ghi[(size_t)MM * RR];
__device__ __half g_u[(size_t)MM * RR];      // fp16 u
__device__ __half g_v[(size_t)MM * RR];      // fp16 v
__device__ float g_g[(size_t)MM * RR];       // gates stay fp32
__device__ float g_part[(size_t)BB * NCH * RR];

// ---------------- PTX helpers (arch-agnostic only) ----------------
__device__ __forceinline__ uint32_t smem_u32(const void* p) {
    uint32_t a;
    asm("{ .reg .u64 t; cvta.to.shared.u64 t, %1; cvt.u32.u64 %0, t; }" : "=r"(a) : "l"(p));
    return a;
}
__device__ __forceinline__ void cp16(uint32_t dst, const void* src) {
    asm volatile("cp.async.cg.shared.global [%0], [%1], 16;" :: "r"(dst), "l"(src));
}
#define CP_COMMIT() asm volatile("cp.async.commit_group;" ::: "memory")
#define CP_WAIT(n)  asm volatile("cp.async.wait_group %0;" :: "n"(n) : "memory")

#define LDSM4(r, addr) \
    asm volatile("ldmatrix.sync.aligned.m8n8.x4.shared.b16 {%0,%1,%2,%3}, [%4];" \
        : "=r"((r)[0]), "=r"((r)[1]), "=r"((r)[2]), "=r"((r)[3]) : "r"(addr))

__device__ __forceinline__ void mma16816(float* c, const uint32_t* a, uint32_t b0, uint32_t b1) {
    asm volatile(
        "mma.sync.aligned.m16n8k16.row.col.f32.f16.f16.f32 "
        "{%0,%1,%2,%3}, {%4,%5,%6,%7}, {%8,%9}, {%0,%1,%2,%3};"
        : "+f"(c[0]), "+f"(c[1]), "+f"(c[2]), "+f"(c[3])
        : "r"(a[0]), "r"(a[1]), "r"(a[2]), "r"(a[3]), "r"(b0), "r"(b1));
}

// SW128 swizzle for 128B rows
__device__ __forceinline__ uint32_t swz(int r, int c) {
    return (uint32_t)(r * 128 + ((c ^ (r & 7)) << 4));
}

// load one 64-K chunk's tiles into a stage. Layout: [A] [B]
template <int TBM_, int A_TILE_>
__device__ __forceinline__ void load_ab(uint32_t st,
                                        const __half* __restrict__ Ahi,
                                        const __half* __restrict__ Bhi,
                                        int K, int row0, int col0, int k0, int tid) {
#pragma unroll
    for (int i = 0; i < TBM_ / 32; i++) {
        int id = tid + i * 256;
        int r = id >> 3, c = id & 7;
        size_t srcoff = (size_t)(row0 + r) * K + k0 + c * 8;
        cp16(st + swz(r, c), Ahi + srcoff);
    }
#pragma unroll
    for (int i = 0; i < 4; i++) {
        int id = tid + i * 256;
        int r = id >> 3, c = id & 7;
        size_t srcoff = (size_t)(col0 + r) * K + k0 + c * 8;
        cp16(st + A_TILE_ + swz(r, c), Bhi + srcoff);
    }
}

// ---------------------------------------------------------------------------
// fp16 warp-MMA GEMM: C[m,n] = sum_k A[m,k]*B[n,k]   (single pass)
// EPI 0: (z + bias) -> fp16 Ohi      (DUAL: z selects B/bias/Ohi2)
// EPI 1: relu(z + bias) -> fp16 Ohi
// EPI 2: g = sigmoid(z + bias); write gbuf(fp32); part = chunk sums of u*g (u fp16 via uh)
// EPI 3: C = depthwise_conv3(x) + z  (fp32 out)
// ---------------------------------------------------------------------------
template <int EPI, bool DUAL, int NWN, int MINB, int NST>
__global__ __launch_bounds__(256, MINB)
void bsgemm(const __half* __restrict__ Ahi,
            const __half* __restrict__ Bhi_,
            const float* __restrict__ bias_,
            float* __restrict__ C,
            __half* __restrict__ Ohi_,
            const __half* __restrict__ Bhi2,
            const float* __restrict__ bias2, __half* __restrict__ Ohi2,
            const __half* __restrict__ uh,
            const float* __restrict__ cw, const float* __restrict__ cb,
            const float* __restrict__ xp,
            float* __restrict__ gbuf, float* __restrict__ part,
            int M, int N, int K) {
    constexpr int TBM_    = 64 * (8 / NWN);
    constexpr int A_TILE_ = TBM_ * 128;
    constexpr int STAGE_  = A_TILE_ + B_TILE;
    constexpr int WNT     = 128 / NWN;
    constexpr int NJ      = WNT / 8;
    constexpr int PB      = NJ / 2;

    extern __shared__ __align__(128) char smem[];
    const uint32_t sb = smem_u32(smem);
    const int tid  = threadIdx.x;
    const int wid  = tid >> 5;
    const int lane = tid & 31;
    const int wm = wid / NWN;
    const int wn = wid % NWN;
    const int row0 = blockIdx.y * TBM_;
    const int col0 = blockIdx.x * 128;
    const int nchunks = K / TBK;

    const __half* Bhi = Bhi_;
    const float* bias = bias_;
    __half* Ohi = Ohi_;
    if (DUAL && blockIdx.z == 1) { Bhi = Bhi2; bias = bias2; Ohi = Ohi2; }

    const int lr = lane & 7;
    const int j  = lane >> 3;
    const int arow  = ((j & 1) << 3) + lr;
    const int acsel = j >> 1;
    const int brow  = ((j >> 1) << 3) + lr;
    const int bcsel = j & 1;

    float acc[4][NJ][4];
#pragma unroll
    for (int mi = 0; mi < 4; mi++)
#pragma unroll
        for (int nj = 0; nj < NJ; nj++)
#pragma unroll
            for (int q = 0; q < 4; q++) acc[mi][nj][q] = 0.0f;

#pragma unroll
    for (int p = 0; p < NST - 1; p++) {
        load_ab<TBM_, A_TILE_>(sb + p * STAGE_, Ahi, Bhi, K, row0, col0, p * TBK, tid);
        CP_COMMIT();
    }

    for (int c = 0; c < nchunks; c++) {
        if (c == nchunks - 1) CP_WAIT(0); else CP_WAIT(NST - 2);
        __syncthreads();

        const int nxt = c + NST - 1;
        if (nxt < nchunks) {
            load_ab<TBM_, A_TILE_>(sb + (nxt % NST) * STAGE_, Ahi, Bhi,
                                   K, row0, col0, nxt * TBK, tid);
            CP_COMMIT();
        }

        const uint32_t sA = sb + (c % NST) * STAGE_;
        const uint32_t sB = sA + A_TILE_;

#pragma unroll
        for (int s = 0; s < 4; s++) {
            uint32_t ah[4][4], bh[PB][4];
#pragma unroll
            for (int mi = 0; mi < 4; mi++) {
                int r = wm * 64 + mi * 16 + arow;
                LDSM4(ah[mi], sA + swz(r, 2 * s + acsel));
            }
#pragma unroll
            for (int p = 0; p < PB; p++) {
                int r = wn * WNT + p * 16 + brow;
                LDSM4(bh[p], sB + swz(r, 2 * s + bcsel));
            }
#pragma unroll
            for (int mi = 0; mi < 4; mi++)
#pragma unroll
                for (int nj = 0; nj < NJ; nj++)
                    mma16816(acc[mi][nj], ah[mi], bh[nj >> 1][(nj & 1) * 2], bh[nj >> 1][(nj & 1) * 2 + 1]);
        }
    }

    // -------- epilogue --------
    const int g_ = lane >> 2, t = lane & 3;
    float psum[NJ][2];
    if (EPI == 2) {
#pragma unroll
        for (int nj = 0; nj < NJ; nj++) { psum[nj][0] = 0.0f; psum[nj][1] = 0.0f; }
    }
#pragma unroll
    for (int mi = 0; mi < 4; mi++) {
#pragma unroll
        for (int nj = 0; nj < NJ; nj++) {
            int row = row0 + wm * 64 + mi * 16 + g_;
            int col = col0 + wn * WNT + nj * 8 + 2 * t;
            size_t i0 = (size_t)row * N + col;
            size_t i1 = (size_t)(row + 8) * N + col;
            float* z = acc[mi][nj];
            if (EPI == 0) {
                float b0 = bias[col], b1 = bias[col + 1];
                *(__half2*)(Ohi + i0) = __halves2half2(__float2half(z[0] + b0), __float2half(z[1] + b1));
                *(__half2*)(Ohi + i1) = __halves2half2(__float2half(z[2] + b0), __float2half(z[3] + b1));
            } else if (EPI == 1) {
                float b0 = bias[col], b1 = bias[col + 1];
                float v0 = fmaxf(z[0] + b0, 0.0f), v1 = fmaxf(z[1] + b1, 0.0f);
                float v2 = fmaxf(z[2] + b0, 0.0f), v3 = fmaxf(z[3] + b1, 0.0f);
                *(__half2*)(Ohi + i0) = __halves2half2(__float2half(v0), __float2half(v1));
                *(__half2*)(Ohi + i1) = __halves2half2(__float2half(v2), __float2half(v3));
            } else if (EPI == 2) {
                float b0 = bias[col], b1 = bias[col + 1];
                float g0 = 1.0f / (1.0f + __expf(-(z[0] + b0)));
                float g1 = 1.0f / (1.0f + __expf(-(z[1] + b1)));
                float g2 = 1.0f / (1.0f + __expf(-(z[2] + b0)));
                float g3 = 1.0f / (1.0f + __expf(-(z[3] + b1)));
                float2 u0 = __half22float2(*(const __half2*)(uh + i0));
                float2 u1 = __half22float2(*(const __half2*)(uh + i1));
                *(float2*)(gbuf + i0) = make_float2(g0, g1);
                *(float2*)(gbuf + i1) = make_float2(g2, g3);
                psum[nj][0] += u0.x * g0 + u1.x * g2;
                psum[nj][1] += u0.y * g1 + u1.y * g3;
            } else {  // EPI == 3: out = conv3(x) + z
                int l0 = row & (LL - 1);
                int l1 = l0 + 8;
                float w0a = cw[3 * col + 0], w1a = cw[3 * col + 1], w2a = cw[3 * col + 2];
                float w0b = cw[3 * col + 3], w1b = cw[3 * col + 4], w2b = cw[3 * col + 5];
                float cb0 = cb[col], cb1 = cb[col + 1];
                const float* xr0 = xp + i0;
                const float* xr1 = xp + i1;
                float2 xc0 = *(const float2*)xr0;
                float2 xc1 = *(const float2*)xr1;
                float2 xq0 = *(const float2*)(xr0 + N);
                float2 xm1 = *(const float2*)(xr1 - N);
                float2 xm0 = (l0 > 0)      ? *(const float2*)(xr0 - N) : make_float2(0.f, 0.f);
                float2 xq1 = (l1 < LL - 1) ? *(const float2*)(xr1 + N) : make_float2(0.f, 0.f);
                float o0 = cb0 + w1a * xc0.x + w2a * xq0.x + z[0] + (l0 > 0 ? w0a * xm0.x : 0.f);
                float o1 = cb1 + w1b * xc0.y + w2b * xq0.y + z[1] + (l0 > 0 ? w0b * xm0.y : 0.f);
                float o2 = cb0 + w1a * xc1.x + w0a * xm1.x + z[2] + (l1 < LL - 1 ? w2a * xq1.x : 0.f);
                float o3 = cb1 + w1b * xc1.y + w0b * xm1.y + z[3] + (l1 < LL - 1 ? w2b * xq1.y : 0.f);
                *(float2*)(C + i0) = make_float2(o0, o1);
                *(float2*)(C + i1) = make_float2(o2, o3);
            }
        }
    }

    if (EPI == 2) {
#pragma unroll
        for (int nj = 0; nj < NJ; nj++) {
#pragma unroll
            for (int k = 0; k < 2; k++) {
                float v = psum[nj][k];
                v += __shfl_xor_sync(0xffffffffu, v, 4);
                v += __shfl_xor_sync(0xffffffffu, v, 8);
                v += __shfl_xor_sync(0xffffffffu, v, 16);
                psum[nj][k] = v;
            }
        }
        __syncthreads();
        float* red = (float*)smem;
        if (lane < 4) {
#pragma unroll
            for (int nj = 0; nj < NJ; nj++) {
                red[wm * 128 + wn * WNT + nj * 8 + 2 * lane + 0] = psum[nj][0];
                red[wm * 128 + wn * WNT + nj * 8 + 2 * lane + 1] = psum[nj][1];
            }
        }
        __syncthreads();
        {
            int ch = tid >> 7, cl = tid & 127;
            if (ch < TBM_ / 128) {
                float s = red[(2 * ch) * 128 + cl] + red[(2 * ch + 1) * 128 + cl];
                int bidx = row0 >> 11;
                int cbase = (row0 & (LL - 1)) >> 7;
                part[((size_t)bidx * NCH + cbase + ch) * (size_t)N + col0 + cl] = s;
            }
        }
    }
}

// ---------------------------------------------------------------------------
// elementwise kernels
// ---------------------------------------------------------------------------
__device__ __forceinline__ uint32_t pack_h(float a, float b) {
    __half2 h = __halves2half2(__float2half(a), __float2half(b));
    return *(uint32_t*)&h;
}

__global__ void split_kernel(const float* __restrict__ s, __half* __restrict__ hi, size_t n) {
    size_t i = ((size_t)blockIdx.x * blockDim.x + threadIdx.x) * 8;
    if (i >= n) return;
    float4 a = *(const float4*)(s + i);
    float4 b = *(const float4*)(s + i + 4);
    uint4 h;
    h.x = pack_h(a.x, a.y); h.y = pack_h(a.z, a.w);
    h.z = pack_h(b.x, b.y); h.w = pack_h(b.z, b.w);
    *(uint4*)(hi + i) = h;
}

__global__ void scanB_kernel(float* __restrict__ part) {
    int tid = blockIdx.x * blockDim.x + threadIdx.x;
    if (tid >= BB * RR) return;
    int r = tid % RR;
    int b = tid / RR;
    float run = 0.0f;
    for (int c = 0; c < NCH; c++) {
        size_t idx = ((size_t)b * NCH + c) * RR + r;
        float t = part[idx];
        part[idx] = run;
        run += t;
    }
}

__global__ void scanC_kernel(const __half* __restrict__ u, const __half* __restrict__ v,
                             const float* __restrict__ g, const float* __restrict__ part,
                             __half* __restrict__ ghi) {
    int tid = blockIdx.x * blockDim.x + threadIdx.x;
    if (tid >= BB * NCH * RR) return;
    int r = tid % RR;
    int c = (tid / RR) % NCH;
    int b = tid / (RR * NCH);
    float acc = part[((size_t)b * NCH + c) * RR + r];
    size_t base = ((size_t)b * LL + c * CHL) * RR + r;
    for (int l = 0; l < CHL; l++) {
        size_t idx = base + (size_t)l * RR;
        float gg = g[idx];
        acc += __half2float(u[idx]) * gg;
        ghi[idx] = __float2half(acc * (__half2float(v[idx]) * gg));
    }
}

// ---------------------------------------------------------------------------
extern "C" void kernel_launch(void* const* d_in, const int* in_sizes, int n_in,
                              void* d_out, int out_size) {
    const float* x      = (const float*)d_in[0];
    const float* Wu     = (const float*)d_in[1];
    const float* bu     = (const float*)d_in[2];
    const float* Wv     = (const float*)d_in[3];
    const float* bv     = (const float*)d_in[4];
    const float* Wg1    = (const float*)d_in[5];
    const float* bg1    = (const float*)d_in[6];
    const float* Wg2    = (const float*)d_in[7];
    const float* bg2    = (const float*)d_in[8];
    const float* conv_w = (const float*)d_in[9];
    const float* conv_b = (const float*)d_in[10];
    float* out = (float*)d_out;

    __half *xhi, *wuhi, *wvhi, *wg1hi, *wg2hi, *hhi, *ghi, *pu, *pv;
    float *pg, *ppart;
    cudaGetSymbolAddress((void**)&xhi, g_xhi);
    cudaGetSymbolAddress((void**)&wuhi, g_wuhi);
    cudaGetSymbolAddress((void**)&wvhi, g_wvhi);
    cudaGetSymbolAddress((void**)&wg1hi, g_wg1hi);
    cudaGetSymbolAddress((void**)&wg2hi, g_wg2hi);
    cudaGetSymbolAddress((void**)&hhi, g_hhi);
    cudaGetSymbolAddress((void**)&ghi, g_ghi);
    cudaGetSymbolAddress((void**)&pu, g_u);        cudaGetSymbolAddress((void**)&pv, g_v);
    cudaGetSymbolAddress((void**)&pg, g_g);        cudaGetSymbolAddress((void**)&ppart, g_part);

    // dual / uv: NWN=4, NST=3 -> 3*32KB = 98304/CTA, 2 CTAs/SM  (R13 config)
    cudaFuncSetAttribute(bsgemm<0,true,4,2,3>,  cudaFuncAttributeMaxDynamicSharedMemorySize, 98304);
    cudaFuncSetAttribute(bsgemm<1,false,2,1,2>, cudaFuncAttributeMaxDynamicSharedMemorySize, 98304);
    cudaFuncSetAttribute(bsgemm<2,false,4,2,2>, cudaFuncAttributeMaxDynamicSharedMemorySize, 65536);
    cudaFuncSetAttribute(bsgemm<3,false,4,2,3>, cudaFuncAttributeMaxDynamicSharedMemorySize, 98304);

    // fp16 conversions
    split_kernel<<<(unsigned)((size_t)MM * DD / 8 / 256), 256>>>(x, xhi, (size_t)MM * DD);
    split_kernel<<<(unsigned)((size_t)RR * DD / 8 / 256), 256>>>(Wu, wuhi, (size_t)RR * DD);
    split_kernel<<<(unsigned)((size_t)RR * DD / 8 / 256), 256>>>(Wv, wvhi, (size_t)RR * DD);

    // dual u/v GEMM (1-pass fp16): z=0 -> u (Wu,bu), z=1 -> v (Wv,bv); fp16 outputs
    bsgemm<0,true,4,2,3><<<dim3(RR / 128, MM / 128, 2), 256, 98304>>>(
        xhi, wuhi, bu, nullptr, pu,
        wvhi, bv, pv, nullptr,
        nullptr, nullptr, nullptr, nullptr, nullptr, MM, RR, DD);

    // gate path (plain fp16)
    split_kernel<<<(unsigned)((size_t)DHH * DD / 8 / 256), 256>>>(Wg1, wg1hi, (size_t)DHH * DD);
    split_kernel<<<(unsigned)((size_t)RR * DHH / 8 / 256), 256>>>(Wg2, wg2hi, (size_t)RR * DHH);
    // h = relu(x Wg1^T + bg1) -> fp16
    bsgemm<1,false,2,1,2><<<dim3(DHH / 128, MM / 256), 256, 98304>>>(
        xhi, wg1hi, bg1, nullptr, hhi,
        nullptr, nullptr, nullptr, nullptr,
        nullptr, nullptr, nullptr, nullptr, nullptr, MM, DHH, DD);
    // gates: write g (fp32), fused chunk partial sums of u*g -> part (u fp16)
    bsgemm<2,false,4,2,2><<<dim3(RR / 128, MM / 128), 256, 65536>>>(
        hhi, wg2hi, bg2, nullptr, nullptr,
        nullptr, nullptr, nullptr, pu,
        nullptr, nullptr, nullptr, pg, ppart, MM, RR, DHH);

    // exclusive prefix over chunks, then apply gates + cumsum + multiply -> fp16
    scanB_kernel<<<(BB * RR + 255) / 256, 256>>>(ppart);
    scanC_kernel<<<(BB * NCH * RR + 255) / 256, 256>>>(pu, pv, pg, ppart, ghi);

    // out = conv3(x) + global_out @ Wu   (1-pass fp16)
    bsgemm<3,false,4,2,3><<<dim3(DD / 128, MM / 128), 256, 98304>>>(
        ghi, wuhi, nullptr, out, nullptr,
        nullptr, nullptr, nullptr, nullptr,
        conv_w, conv_b, x, nullptr, nullptr, MM, DD, RR);
}

// round 16
// speedup vs baseline: 1.1311x; 1.0029x over previous
#include <cuda_runtime.h>
#include <cuda_fp16.h>
#include <cstdint>
#include <math.h>

// ---------------- problem constants ----------------
#define BB 4
#define LL 2048
#define DD 2048
#define RR 2048
#define DHH 512
#define MM (BB * LL)          // 8192
#define NCH 16
#define CHL (LL / NCH)        // 128

#define TBK 64
#define B_TILE 16384          // 128 rows * 128B

// ---------------- device scratch ----------------
__device__ __half g_xhi[(size_t)MM * DD];
__device__ __half g_wuhi[(size_t)RR * DD];
__device__ __half g_wvhi[(size_t)RR * DD];
__device__ __half g_wg1hi[(size_t)DHH * DD];
__device__ __half g_wg2hi[(size_t)RR * DHH];
__device__ __half g_hhi[(size_t)MM * DHH];
__device__ __half g_ghi[(size_t)MM * RR];
__device__ __half g_u[(size_t)MM * RR];      // fp16 u
__device__ __half g_v[(size_t)MM * RR];      // fp16 v
__device__ __half g_ug[(size_t)MM * RR];     // fp16 u*g
__device__ __half g_vg[(size_t)MM * RR];     // fp16 v*g
__device__ float g_part[(size_t)BB * NCH * RR];

// ---------------- PTX helpers (arch-agnostic only) ----------------
__device__ __forceinline__ uint32_t smem_u32(const void* p) {
    uint32_t a;
    asm("{ .reg .u64 t; cvta.to.shared.u64 t, %1; cvt.u32.u64 %0, t; }" : "=r"(a) : "l"(p));
    return a;
}
__device__ __forceinline__ void cp16(uint32_t dst, const void* src) {
    asm volatile("cp.async.cg.shared.global [%0], [%1], 16;" :: "r"(dst), "l"(src));
}
#define CP_COMMIT() asm volatile("cp.async.commit_group;" ::: "memory")
#define CP_WAIT(n)  asm volatile("cp.async.wait_group %0;" :: "n"(n) : "memory")

#define LDSM4(r, addr) \
    asm volatile("ldmatrix.sync.aligned.m8n8.x4.shared.b16 {%0,%1,%2,%3}, [%4];" \
        : "=r"((r)[0]), "=r"((r)[1]), "=r"((r)[2]), "=r"((r)[3]) : "r"(addr))

__device__ __forceinline__ void mma16816(float* c, const uint32_t* a, uint32_t b0, uint32_t b1) {
    asm volatile(
        "mma.sync.aligned.m16n8k16.row.col.f32.f16.f16.f32 "
        "{%0,%1,%2,%3}, {%4,%5,%6,%7}, {%8,%9}, {%0,%1,%2,%3};"
        : "+f"(c[0]), "+f"(c[1]), "+f"(c[2]), "+f"(c[3])
        : "r"(a[0]), "r"(a[1]), "r"(a[2]), "r"(a[3]), "r"(b0), "r"(b1));
}

// SW128 swizzle for 128B rows
__device__ __forceinline__ uint32_t swz(int r, int c) {
    return (uint32_t)(r * 128 + ((c ^ (r & 7)) << 4));
}

// ---------------------------------------------------------------------------
// Dual-output GEMM: U = A Wu^T + bu, V = A Wv^T + bv  (fp16 outputs)
// CTA 128x128 per output, 8 warps (2 wm x 4 wn), warp tile 64x32 per output.
// A loaded once per CTA -> feeds both outputs (128B LDS per MMA).
// Stage: [A 16KB][Bu 16KB][Bv 16KB] = 48KB, NST=4 -> 196608 B, 1 CTA/SM.
// ---------------------------------------------------------------------------
#define DUO_STAGE 49152
#define DUO_NST 4
__global__ __launch_bounds__(256, 1)
void duogemm(const __half* __restrict__ A,
             const __half* __restrict__ Bu, const __half* __restrict__ Bv,
             const float* __restrict__ bu, const float* __restrict__ bv,
             __half* __restrict__ U, __half* __restrict__ V,
             int M, int N, int K) {
    extern __shared__ __align__(128) char smem[];
    const uint32_t sb = smem_u32(smem);
    const int tid  = threadIdx.x;
    const int wid  = tid >> 5;
    const int lane = tid & 31;
    const int wm = wid >> 2;          // 0..1
    const int wn = wid & 3;           // 0..3
    const int row0 = blockIdx.y * 128;
    const int col0 = blockIdx.x * 128;
    const int nchunks = K / TBK;

    const int lr = lane & 7;
    const int j  = lane >> 3;
    const int arow  = ((j & 1) << 3) + lr;
    const int acsel = j >> 1;
    const int brow  = ((j >> 1) << 3) + lr;
    const int bcsel = j & 1;

    float acc[2][4][4][4];            // [out][mi][nj][q]
#pragma unroll
    for (int o = 0; o < 2; o++)
#pragma unroll
        for (int mi = 0; mi < 4; mi++)
#pragma unroll
            for (int nj = 0; nj < 4; nj++)
#pragma unroll
                for (int q = 0; q < 4; q++) acc[o][mi][nj][q] = 0.0f;

    auto load_chunk = [&](int stage, int k0) {
        uint32_t st = sb + stage * DUO_STAGE;
#pragma unroll
        for (int i = 0; i < 4; i++) {
            int id = tid + i * 256;
            int r = id >> 3, c = id & 7;
            size_t off = (size_t)(row0 + r) * K + k0 + c * 8;
            cp16(st + swz(r, c), A + off);
        }
#pragma unroll
        for (int i = 0; i < 4; i++) {
            int id = tid + i * 256;
            int r = id >> 3, c = id & 7;
            size_t off = (size_t)(col0 + r) * K + k0 + c * 8;
            cp16(st + 16384 + swz(r, c), Bu + off);
            cp16(st + 32768 + swz(r, c), Bv + off);
        }
    };

#pragma unroll
    for (int p = 0; p < DUO_NST - 1; p++) {
        load_chunk(p, p * TBK);
        CP_COMMIT();
    }

    for (int c = 0; c < nchunks; c++) {
        if (c == nchunks - 1) CP_WAIT(0); else CP_WAIT(DUO_NST - 2);
        __syncthreads();

        const int nxt = c + DUO_NST - 1;
        if (nxt < nchunks) {
            load_chunk(nxt % DUO_NST, nxt * TBK);
            CP_COMMIT();
        }

        const uint32_t sA = sb + (c % DUO_NST) * DUO_STAGE;
        const uint32_t sU = sA + 16384;
        const uint32_t sV = sA + 32768;

#pragma unroll
        for (int s = 0; s < 4; s++) {
            uint32_t ah[4][4], bhu[2][4], bhv[2][4];
#pragma unroll
            for (int mi = 0; mi < 4; mi++) {
                int r = wm * 64 + mi * 16 + arow;
                LDSM4(ah[mi], sA + swz(r, 2 * s + acsel));
            }
#pragma unroll
            for (int p = 0; p < 2; p++) {
                int r = wn * 32 + p * 16 + brow;
                uint32_t so = swz(r, 2 * s + bcsel);
                LDSM4(bhu[p], sU + so);
                LDSM4(bhv[p], sV + so);
            }
#pragma unroll
            for (int mi = 0; mi < 4; mi++)
#pragma unroll
                for (int nj = 0; nj < 4; nj++) {
                    mma16816(acc[0][mi][nj], ah[mi], bhu[nj >> 1][(nj & 1) * 2], bhu[nj >> 1][(nj & 1) * 2 + 1]);
                    mma16816(acc[1][mi][nj], ah[mi], bhv[nj >> 1][(nj & 1) * 2], bhv[nj >> 1][(nj & 1) * 2 + 1]);
                }
        }
    }

    // epilogue: fp16 stores with bias
    const int g_ = lane >> 2, t = lane & 3;
#pragma unroll
    for (int mi = 0; mi < 4; mi++) {
#pragma unroll
        for (int nj = 0; nj < 4; nj++) {
            int row = row0 + wm * 64 + mi * 16 + g_;
            int col = col0 + wn * 32 + nj * 8 + 2 * t;
            size_t i0 = (size_t)row * N + col;
            size_t i1 = (size_t)(row + 8) * N + col;
            float bu0 = bu[col], bu1 = bu[col + 1];
            float bv0 = bv[col], bv1 = bv[col + 1];
            float* zu = acc[0][mi][nj];
            float* zv = acc[1][mi][nj];
            *(__half2*)(U + i0) = __floats2half2_rn(zu[0] + bu0, zu[1] + bu1);
            *(__half2*)(U + i1) = __floats2half2_rn(zu[2] + bu0, zu[3] + bu1);
            *(__half2*)(V + i0) = __floats2half2_rn(zv[0] + bv0, zv[1] + bv1);
            *(__half2*)(V + i1) = __floats2half2_rn(zv[2] + bv0, zv[3] + bv1);
        }
    }
}

// ---------------------------------------------------------------------------
// Single-output fp16 GEMM (h / gates / uv paths)
// EPI 1: relu(z + bias) -> fp16 Ohi
// EPI 2: g = sigmoid(z + bias); write ug,vg (fp16); part = chunk sums of ug
// EPI 3: C = depthwise_conv3(x) + z  (fp32 out)
// ---------------------------------------------------------------------------
template <int EPI, int NWN, int MINB, int NST>
__global__ __launch_bounds__(256, MINB)
void bsgemm(const __half* __restrict__ Ahi,
            const __half* __restrict__ Bhi,
            const float* __restrict__ bias,
            float* __restrict__ C,
            __half* __restrict__ Ohi,
            const __half* __restrict__ uh, const __half* __restrict__ vh,
            __half* __restrict__ ugb, __half* __restrict__ vgb,
            const float* __restrict__ cw, const float* __restrict__ cb,
            const float* __restrict__ xp,
            float* __restrict__ part,
            int M, int N, int K) {
    constexpr int TBM_    = 64 * (8 / NWN);
    constexpr int A_TILE_ = TBM_ * 128;
    constexpr int STAGE_  = A_TILE_ + B_TILE;
    constexpr int WNT     = 128 / NWN;
    constexpr int NJ      = WNT / 8;
    constexpr int PB      = NJ / 2;

    extern __shared__ __align__(128) char smem[];
    const uint32_t sb = smem_u32(smem);
    const int tid  = threadIdx.x;
    const int wid  = tid >> 5;
    const int lane = tid & 31;
    const int wm = wid / NWN;
    const int wn = wid % NWN;
    const int row0 = blockIdx.y * TBM_;
    const int col0 = blockIdx.x * 128;
    const int nchunks = K / TBK;

    const int lr = lane & 7;
    const int j  = lane >> 3;
    const int arow  = ((j & 1) << 3) + lr;
    const int acsel = j >> 1;
    const int brow  = ((j >> 1) << 3) + lr;
    const int bcsel = j & 1;

    float acc[4][NJ][4];
#pragma unroll
    for (int mi = 0; mi < 4; mi++)
#pragma unroll
        for (int nj = 0; nj < NJ; nj++)
#pragma unroll
            for (int q = 0; q < 4; q++) acc[mi][nj][q] = 0.0f;

    auto load_chunk = [&](int stage, int k0) {
        uint32_t st = sb + stage * STAGE_;
#pragma unroll
        for (int i = 0; i < TBM_ / 32; i++) {
            int id = tid + i * 256;
            int r = id >> 3, c = id & 7;
            size_t off = (size_t)(row0 + r) * K + k0 + c * 8;
            cp16(st + swz(r, c), Ahi + off);
        }
#pragma unroll
        for (int i = 0; i < 4; i++) {
            int id = tid + i * 256;
            int r = id >> 3, c = id & 7;
            size_t off = (size_t)(col0 + r) * K + k0 + c * 8;
            cp16(st + A_TILE_ + swz(r, c), Bhi + off);
        }
    };

#pragma unroll
    for (int p = 0; p < NST - 1; p++) {
        load_chunk(p, p * TBK);
        CP_COMMIT();
    }

    for (int c = 0; c < nchunks; c++) {
        if (c == nchunks - 1) CP_WAIT(0); else CP_WAIT(NST - 2);
        __syncthreads();

        const int nxt = c + NST - 1;
        if (nxt < nchunks) {
            load_chunk(nxt % NST, nxt * TBK);
            CP_COMMIT();
        }

        const uint32_t sA = sb + (c % NST) * STAGE_;
        const uint32_t sB = sA + A_TILE_;

#pragma unroll
        for (int s = 0; s < 4; s++) {
            uint32_t ah[4][4], bh[PB][4];
#pragma unroll
            for (int mi = 0; mi < 4; mi++) {
                int r = wm * 64 + mi * 16 + arow;
                LDSM4(ah[mi], sA + swz(r, 2 * s + acsel));
            }
#pragma unroll
            for (int p = 0; p < PB; p++) {
                int r = wn * WNT + p * 16 + brow;
                LDSM4(bh[p], sB + swz(r, 2 * s + bcsel));
            }
#pragma unroll
            for (int mi = 0; mi < 4; mi++)
#pragma unroll
                for (int nj = 0; nj < NJ; nj++)
                    mma16816(acc[mi][nj], ah[mi], bh[nj >> 1][(nj & 1) * 2], bh[nj >> 1][(nj & 1) * 2 + 1]);
        }
    }

    // -------- epilogue --------
    const int g_ = lane >> 2, t = lane & 3;
    float psum[NJ][2];
    if (EPI == 2) {
#pragma unroll
        for (int nj = 0; nj < NJ; nj++) { psum[nj][0] = 0.0f; psum[nj][1] = 0.0f; }
    }
#pragma unroll
    for (int mi = 0; mi < 4; mi++) {
#pragma unroll
        for (int nj = 0; nj < NJ; nj++) {
            int row = row0 + wm * 64 + mi * 16 + g_;
            int col = col0 + wn * WNT + nj * 8 + 2 * t;
            size_t i0 = (size_t)row * N + col;
            size_t i1 = (size_t)(row + 8) * N + col;
            float* z = acc[mi][nj];
            if (EPI == 1) {
                float b0 = bias[col], b1 = bias[col + 1];
                *(__half2*)(Ohi + i0) = __floats2half2_rn(fmaxf(z[0] + b0, 0.f), fmaxf(z[1] + b1, 0.f));
                *(__half2*)(Ohi + i1) = __floats2half2_rn(fmaxf(z[2] + b0, 0.f), fmaxf(z[3] + b1, 0.f));
            } else if (EPI == 2) {
                float b0 = bias[col], b1 = bias[col + 1];
                float g0 = 1.0f / (1.0f + __expf(-(z[0] + b0)));
                float g1 = 1.0f / (1.0f + __expf(-(z[1] + b1)));
                float g2 = 1.0f / (1.0f + __expf(-(z[2] + b0)));
                float g3 = 1.0f / (1.0f + __expf(-(z[3] + b1)));
                float2 u0 = __half22float2(*(const __half2*)(uh + i0));
                float2 u1 = __half22float2(*(const __half2*)(uh + i1));
                float2 v0 = __half22float2(*(const __half2*)(vh + i0));
                float2 v1 = __half22float2(*(const __half2*)(vh + i1));
                __half2 ug0 = __floats2half2_rn(u0.x * g0, u0.y * g1);
                __half2 ug1 = __floats2half2_rn(u1.x * g2, u1.y * g3);
                *(__half2*)(ugb + i0) = ug0;
                *(__half2*)(ugb + i1) = ug1;
                *(__half2*)(vgb + i0) = __floats2half2_rn(v0.x * g0, v0.y * g1);
                *(__half2*)(vgb + i1) = __floats2half2_rn(v1.x * g2, v1.y * g3);
                float2 r0 = __half22float2(ug0), r1 = __half22float2(ug1);
                psum[nj][0] += r0.x + r1.x;
                psum[nj][1] += r0.y + r1.y;
            } else {  // EPI == 3: out = conv3(x) + z
                int l0 = row & (LL - 1);
                int l1 = l0 + 8;
                float w0a = cw[3 * col + 0], w1a = cw[3 * col + 1], w2a = cw[3 * col + 2];
                float w0b = cw[3 * col + 3], w1b = cw[3 * col + 4], w2b = cw[3 * col + 5];
                float cb0 = cb[col], cb1 = cb[col + 1];
                const float* xr0 = xp + i0;
                const float* xr1 = xp + i1;
                float2 xc0 = *(const float2*)xr0;
                float2 xc1 = *(const float2*)xr1;
                float2 xq0 = *(const float2*)(xr0 + N);
                float2 xm1 = *(const float2*)(xr1 - N);
                float2 xm0 = (l0 > 0)      ? *(const float2*)(xr0 - N) : make_float2(0.f, 0.f);
                float2 xq1 = (l1 < LL - 1) ? *(const float2*)(xr1 + N) : make_float2(0.f, 0.f);
                float o0 = cb0 + w1a * xc0.x + w2a * xq0.x + z[0] + (l0 > 0 ? w0a * xm0.x : 0.f);
                float o1 = cb1 + w1b * xc0.y + w2b * xq0.y + z[1] + (l0 > 0 ? w0b * xm0.y : 0.f);
                float o2 = cb0 + w1a * xc1.x + w0a * xm1.x + z[2] + (l1 < LL - 1 ? w2a * xq1.x : 0.f);
                float o3 = cb1 + w1b * xc1.y + w0b * xm1.y + z[3] + (l1 < LL - 1 ? w2b * xq1.y : 0.f);
                *(float2*)(C + i0) = make_float2(o0, o1);
                *(float2*)(C + i1) = make_float2(o2, o3);
            }
        }
    }

    if (EPI == 2) {
#pragma unroll
        for (int nj = 0; nj < NJ; nj++) {
#pragma unroll
            for (int k = 0; k < 2; k++) {
                float v = psum[nj][k];
                v += __shfl_xor_sync(0xffffffffu, v, 4);
                v += __shfl_xor_sync(0xffffffffu, v, 8);
                v += __shfl_xor_sync(0xffffffffu, v, 16);
                psum[nj][k] = v;
            }
        }
        __syncthreads();
        float* red = (float*)smem;
        if (lane < 4) {
#pragma unroll
            for (int nj = 0; nj < NJ; nj++) {
                red[wm * 128 + wn * WNT + nj * 8 + 2 * lane + 0] = psum[nj][0];
                red[wm * 128 + wn * WNT + nj * 8 + 2 * lane + 1] = psum[nj][1];
            }
        }
        __syncthreads();
        {
            int ch = tid >> 7, cl = tid & 127;
            if (ch < TBM_ / 128) {
                float s = red[(2 * ch) * 128 + cl] + red[(2 * ch + 1) * 128 + cl];
                int bidx = row0 >> 11;
                int cbase = (row0 & (LL - 1)) >> 7;
                part[((size_t)bidx * NCH + cbase + ch) * (size_t)N + col0 + cl] = s;
            }
        }
    }
}

// ---------------------------------------------------------------------------
// elementwise kernels
// ---------------------------------------------------------------------------
__device__ __forceinline__ uint32_t pack_h(float a, float b) {
    __half2 h = __halves2half2(__float2half(a), __float2half(b));
    return *(uint32_t*)&h;
}

__global__ void split_kernel(const float* __restrict__ s, __half* __restrict__ hi, size_t n) {
    size_t i = ((size_t)blockIdx.x * blockDim.x + threadIdx.x) * 8;
    if (i >= n) return;
    float4 a = *(const float4*)(s + i);
    float4 b = *(const float4*)(s + i + 4);
    uint4 h;
    h.x = pack_h(a.x, a.y); h.y = pack_h(a.z, a.w);
    h.z = pack_h(b.x, b.y); h.w = pack_h(b.z, b.w);
    *(uint4*)(hi + i) = h;
}

__global__ void scanB_kernel(float* __restrict__ part) {
    int tid = blockIdx.x * blockDim.x + threadIdx.x;
    if (tid >= BB * RR) return;
    int r = tid % RR;
    int b = tid / RR;
    float run = 0.0f;
    for (int c = 0; c < NCH; c++) {
        size_t idx = ((size_t)b * NCH + c) * RR + r;
        float t = part[idx];
        part[idx] = run;
        run += t;
    }
}

__global__ void scanC_kernel(const __half* __restrict__ ug, const __half* __restrict__ vg,
                             const float* __restrict__ part,
                             __half* __restrict__ ghi) {
    int tid = blockIdx.x * blockDim.x + threadIdx.x;
    if (tid >= BB * NCH * RR) return;
    int r = tid % RR;
    int c = (tid / RR) % NCH;
    int b = tid / (RR * NCH);
    float acc = part[((size_t)b * NCH + c) * RR + r];
    size_t base = ((size_t)b * LL + c * CHL) * RR + r;
    for (int l = 0; l < CHL; l++) {
        size_t idx = base + (size_t)l * RR;
        acc += __half2float(ug[idx]);
        ghi[idx] = __float2half(acc * __half2float(vg[idx]));
    }
}

// ---------------------------------------------------------------------------
extern "C" void kernel_launch(void* const* d_in, const int* in_sizes, int n_in,
                              void* d_out, int out_size) {
    const float* x      = (const float*)d_in[0];
    const float* Wu     = (const float*)d_in[1];
    const float* bu     = (const float*)d_in[2];
    const float* Wv     = (const float*)d_in[3];
    const float* bv     = (const float*)d_in[4];
    const float* Wg1    = (const float*)d_in[5];
    const float* bg1    = (const float*)d_in[6];
    const float* Wg2    = (const float*)d_in[7];
    const float* bg2    = (const float*)d_in[8];
    const float* conv_w = (const float*)d_in[9];
    const float* conv_b = (const float*)d_in[10];
    float* out = (float*)d_out;

    __half *xhi, *wuhi, *wvhi, *wg1hi, *wg2hi, *hhi, *ghi, *pu, *pv, *pug, *pvg;
    float *ppart;
    cudaGetSymbolAddress((void**)&xhi, g_xhi);
    cudaGetSymbolAddress((void**)&wuhi, g_wuhi);
    cudaGetSymbolAddress((void**)&wvhi, g_wvhi);
    cudaGetSymbolAddress((void**)&wg1hi, g_wg1hi);
    cudaGetSymbolAddress((void**)&wg2hi, g_wg2hi);
    cudaGetSymbolAddress((void**)&hhi, g_hhi);
    cudaGetSymbolAddress((void**)&ghi, g_ghi);
    cudaGetSymbolAddress((void**)&pu, g_u);        cudaGetSymbolAddress((void**)&pv, g_v);
    cudaGetSymbolAddress((void**)&pug, g_ug);      cudaGetSymbolAddress((void**)&pvg, g_vg);
    cudaGetSymbolAddress((void**)&ppart, g_part);

    cudaFuncSetAttribute(duogemm,          cudaFuncAttributeMaxDynamicSharedMemorySize, DUO_NST * DUO_STAGE);
    cudaFuncSetAttribute(bsgemm<1,2,1,2>,  cudaFuncAttributeMaxDynamicSharedMemorySize, 98304);
    cudaFuncSetAttribute(bsgemm<2,4,2,2>,  cudaFuncAttributeMaxDynamicSharedMemorySize, 65536);
    cudaFuncSetAttribute(bsgemm<3,4,2,3>,  cudaFuncAttributeMaxDynamicSharedMemorySize, 98304);

    // fp16 conversions
    split_kernel<<<(unsigned)((size_t)MM * DD / 8 / 256), 256>>>(x, xhi, (size_t)MM * DD);
    split_kernel<<<(unsigned)((size_t)RR * DD / 8 / 256), 256>>>(Wu, wuhi, (size_t)RR * DD);
    split_kernel<<<(unsigned)((size_t)RR * DD / 8 / 256), 256>>>(Wv, wvhi, (size_t)RR * DD);

    // dual-output u/v GEMM: A loaded once, both weights per stage
    duogemm<<<dim3(RR / 128, MM / 128), 256, DUO_NST * DUO_STAGE>>>(
        xhi, wuhi, wvhi, bu, bv, pu, pv, MM, RR, DD);

    // gate path (plain fp16)
    split_kernel<<<(unsigned)((size_t)DHH * DD / 8 / 256), 256>>>(Wg1, wg1hi, (size_t)DHH * DD);
    split_kernel<<<(unsigned)((size_t)RR * DHH / 8 / 256), 256>>>(Wg2, wg2hi, (size_t)RR * DHH);
    // h = relu(x Wg1^T + bg1) -> fp16
    bsgemm<1,2,1,2><<<dim3(DHH / 128, MM / 256), 256, 98304>>>(
        xhi, wg1hi, bg1, nullptr, hhi,
        nullptr, nullptr, nullptr, nullptr,
        nullptr, nullptr, nullptr, nullptr, MM, DHH, DD);
    // gates: compute g, write ug/vg fp16, chunk partial sums of ug -> part
    bsgemm<2,4,2,2><<<dim3(RR / 128, MM / 128), 256, 65536>>>(
        hhi, wg2hi, bg2, nullptr, nullptr,
        pu, pv, pug, pvg,
        nullptr, nullptr, nullptr, ppart, MM, RR, DHH);

    // exclusive prefix over chunks, then cumsum + multiply -> fp16
    scanB_kernel<<<(BB * RR + 255) / 256, 256>>>(ppart);
    scanC_kernel<<<(BB * NCH * RR + 255) / 256, 256>>>(pug, pvg, ppart, ghi);

    // out = conv3(x) + global_out @ Wu
    bsgemm<3,4,2,3><<<dim3(DD / 128, MM / 128), 256, 98304>>>(
        ghi, wuhi, nullptr, out, nullptr,
        nullptr, nullptr, nullptr, nullptr,
        conv_w, conv_b, x, nullptr, MM, DD, RR);
}

// round 17
// speedup vs baseline: 1.1650x; 1.0299x over previous
#include <cuda_runtime.h>
#include <cuda_fp16.h>
#include <cstdint>
#include <math.h>

// ---------------- problem constants ----------------
#define BB 4
#define LL 2048
#define DD 2048
#define RR 2048
#define DHH 512
#define MM (BB * LL)          // 8192
#define NCH 16
#define CHL (LL / NCH)        // 128

#define TBK 64
#define B_TILE 16384          // 128 rows * 128B

// ---------------- device scratch ----------------
__device__ __half g_xhi[(size_t)MM * DD];
__device__ __half g_wuhi[(size_t)RR * DD];
__device__ __half g_wvhi[(size_t)RR * DD];
__device__ __half g_wg1hi[(size_t)DHH * DD];
__device__ __half g_wg2hi[(size_t)RR * DHH];
__device__ __half g_hhi[(size_t)MM * DHH];
__device__ __half g_ghi[(size_t)MM * RR];
__device__ __half g_u[(size_t)MM * RR];      // fp16 u
__device__ __half g_v[(size_t)MM * RR];      // fp16 v
__device__ __half g_ug[(size_t)MM * RR];     // fp16 u*g
__device__ __half g_vg[(size_t)MM * RR];     // fp16 v*g
__device__ float g_part[(size_t)BB * NCH * RR];

// ---------------- PTX helpers (arch-agnostic only) ----------------
__device__ __forceinline__ uint32_t smem_u32(const void* p) {
    uint32_t a;
    asm("{ .reg .u64 t; cvta.to.shared.u64 t, %1; cvt.u32.u64 %0, t; }" : "=r"(a) : "l"(p));
    return a;
}
__device__ __forceinline__ void cp16(uint32_t dst, const void* src) {
    asm volatile("cp.async.cg.shared.global [%0], [%1], 16;" :: "r"(dst), "l"(src));
}
#define CP_COMMIT() asm volatile("cp.async.commit_group;" ::: "memory")
#define CP_WAIT(n)  asm volatile("cp.async.wait_group %0;" :: "n"(n) : "memory")

#define LDSM4(r, addr) \
    asm volatile("ldmatrix.sync.aligned.m8n8.x4.shared.b16 {%0,%1,%2,%3}, [%4];" \
        : "=r"((r)[0]), "=r"((r)[1]), "=r"((r)[2]), "=r"((r)[3]) : "r"(addr))

__device__ __forceinline__ void mma16816(float* c, const uint32_t* a, uint32_t b0, uint32_t b1) {
    asm volatile(
        "mma.sync.aligned.m16n8k16.row.col.f32.f16.f16.f32 "
        "{%0,%1,%2,%3}, {%4,%5,%6,%7}, {%8,%9}, {%0,%1,%2,%3};"
        : "+f"(c[0]), "+f"(c[1]), "+f"(c[2]), "+f"(c[3])
        : "r"(a[0]), "r"(a[1]), "r"(a[2]), "r"(a[3]), "r"(b0), "r"(b1));
}

// SW128 swizzle for 128B rows
__device__ __forceinline__ uint32_t swz(int r, int c) {
    return (uint32_t)(r * 128 + ((c ^ (r & 7)) << 4));
}
// swizzle for rows of NKC*128 bytes (each 128B half keeps SW128 pattern)
template <int NKC>
__device__ __forceinline__ uint32_t swzk(int r, int c) {
    return (uint32_t)(r * (128 * NKC) + ((c >> 3) << 7) + ((((c & 7) ^ (r & 7))) << 4));
}

// ---------------------------------------------------------------------------
// Dual-output GEMM: U = A Wu^T + bu, V = A Wv^T + bv  (fp16 outputs)
// CTA 128x128 per output, 8 warps (2 wm x 4 wn), warp tile 64x32 per output.
// TBK=128 (NKC=2): 16 chunks, half the barrier bubbles of TBK=64.
// Stage: [A 32KB][Bu 32KB][Bv 32KB] = 96KB, NST=2 -> 196608 B, 1 CTA/SM.
// ---------------------------------------------------------------------------
#define DUO_NKC 2
#define DUO_TBK (64 * DUO_NKC)
#define DUO_A 32768
#define DUO_STAGE (3 * DUO_A)   // 98304
#define DUO_NST 2
__global__ __launch_bounds__(256, 1)
void duogemm(const __half* __restrict__ A,
             const __half* __restrict__ Bu, const __half* __restrict__ Bv,
             const float* __restrict__ bu, const float* __restrict__ bv,
             __half* __restrict__ U, __half* __restrict__ V,
             int M, int N, int K) {
    extern __shared__ __align__(128) char smem[];
    const uint32_t sb = smem_u32(smem);
    const int tid  = threadIdx.x;
    const int wid  = tid >> 5;
    const int lane = tid & 31;
    const int wm = wid >> 2;          // 0..1
    const int wn = wid & 3;           // 0..3
    const int row0 = blockIdx.y * 128;
    const int col0 = blockIdx.x * 128;
    const int nchunks = K / DUO_TBK;  // 16

    const int lr = lane & 7;
    const int j  = lane >> 3;
    const int arow  = ((j & 1) << 3) + lr;
    const int acsel = j >> 1;
    const int brow  = ((j >> 1) << 3) + lr;
    const int bcsel = j & 1;

    float acc[2][4][4][4];            // [out][mi][nj][q]
#pragma unroll
    for (int o = 0; o < 2; o++)
#pragma unroll
        for (int mi = 0; mi < 4; mi++)
#pragma unroll
            for (int nj = 0; nj < 4; nj++)
#pragma unroll
                for (int q = 0; q < 4; q++) acc[o][mi][nj][q] = 0.0f;

    auto load_chunk = [&](int stage, int k0) {
        uint32_t st = sb + stage * DUO_STAGE;
#pragma unroll
        for (int i = 0; i < 8; i++) {            // 128 rows x 16 chunks of 16B
            int id = tid + i * 256;
            int r = id >> 4, c = id & 15;
            size_t off = (size_t)(row0 + r) * K + k0 + c * 8;
            cp16(st + swzk<DUO_NKC>(r, c), A + off);
        }
#pragma unroll
        for (int i = 0; i < 8; i++) {
            int id = tid + i * 256;
            int r = id >> 4, c = id & 15;
            size_t off = (size_t)(col0 + r) * K + k0 + c * 8;
            cp16(st + DUO_A     + swzk<DUO_NKC>(r, c), Bu + off);
            cp16(st + 2 * DUO_A + swzk<DUO_NKC>(r, c), Bv + off);
        }
    };

    load_chunk(0, 0);
    CP_COMMIT();

    for (int c = 0; c < nchunks; c++) {
        CP_WAIT(0);
        __syncthreads();

        if (c + 1 < nchunks) {
            load_chunk((c + 1) & 1, (c + 1) * DUO_TBK);
            CP_COMMIT();
        }

        const uint32_t sA = sb + (c & 1) * DUO_STAGE;
        const uint32_t sU = sA + DUO_A;
        const uint32_t sV = sA + 2 * DUO_A;

#pragma unroll
        for (int s = 0; s < 4 * DUO_NKC; s++) {
            uint32_t ah[4][4], bhu[2][4], bhv[2][4];
#pragma unroll
            for (int mi = 0; mi < 4; mi++) {
                int r = wm * 64 + mi * 16 + arow;
                LDSM4(ah[mi], sA + swzk<DUO_NKC>(r, 2 * s + acsel));
            }
#pragma unroll
            for (int p = 0; p < 2; p++) {
                int r = wn * 32 + p * 16 + brow;
                uint32_t so = swzk<DUO_NKC>(r, 2 * s + bcsel);
                LDSM4(bhu[p], sU + so);
                LDSM4(bhv[p], sV + so);
            }
#pragma unroll
            for (int mi = 0; mi < 4; mi++)
#pragma unroll
                for (int nj = 0; nj < 4; nj++) {
                    mma16816(acc[0][mi][nj], ah[mi], bhu[nj >> 1][(nj & 1) * 2], bhu[nj >> 1][(nj & 1) * 2 + 1]);
                    mma16816(acc[1][mi][nj], ah[mi], bhv[nj >> 1][(nj & 1) * 2], bhv[nj >> 1][(nj & 1) * 2 + 1]);
                }
        }
    }

    // epilogue: fp16 stores with bias
    const int g_ = lane >> 2, t = lane & 3;
#pragma unroll
    for (int mi = 0; mi < 4; mi++) {
#pragma unroll
        for (int nj = 0; nj < 4; nj++) {
            int row = row0 + wm * 64 + mi * 16 + g_;
            int col = col0 + wn * 32 + nj * 8 + 2 * t;
            size_t i0 = (size_t)row * N + col;
            size_t i1 = (size_t)(row + 8) * N + col;
            float bu0 = bu[col], bu1 = bu[col + 1];
            float bv0 = bv[col], bv1 = bv[col + 1];
            float* zu = acc[0][mi][nj];
            float* zv = acc[1][mi][nj];
            *(__half2*)(U + i0) = __floats2half2_rn(zu[0] + bu0, zu[1] + bu1);
            *(__half2*)(U + i1) = __floats2half2_rn(zu[2] + bu0, zu[3] + bu1);
            *(__half2*)(V + i0) = __floats2half2_rn(zv[0] + bv0, zv[1] + bv1);
            *(__half2*)(V + i1) = __floats2half2_rn(zv[2] + bv0, zv[3] + bv1);
        }
    }
}

// ---------------------------------------------------------------------------
// Single-output fp16 GEMM (h / gates / uv paths)
// EPI 1: relu(z + bias) -> fp16 Ohi
// EPI 2: g = sigmoid(z + bias); write ug,vg (fp16); part = chunk sums of ug
// EPI 3: C = depthwise_conv3(x) + z  (fp32 out)
// ---------------------------------------------------------------------------
template <int EPI, int NWN, int MINB, int NST>
__global__ __launch_bounds__(256, MINB)
void bsgemm(const __half* __restrict__ Ahi,
            const __half* __restrict__ Bhi,
            const float* __restrict__ bias,
            float* __restrict__ C,
            __half* __restrict__ Ohi,
            const __half* __restrict__ uh, const __half* __restrict__ vh,
            __half* __restrict__ ugb, __half* __restrict__ vgb,
            const float* __restrict__ cw, const float* __restrict__ cb,
            const float* __restrict__ xp,
            float* __restrict__ part,
            int M, int N, int K) {
    constexpr int TBM_    = 64 * (8 / NWN);
    constexpr int A_TILE_ = TBM_ * 128;
    constexpr int STAGE_  = A_TILE_ + B_TILE;
    constexpr int WNT     = 128 / NWN;
    constexpr int NJ      = WNT / 8;
    constexpr int PB      = NJ / 2;

    extern __shared__ __align__(128) char smem[];
    const uint32_t sb = smem_u32(smem);
    const int tid  = threadIdx.x;
    const int wid  = tid >> 5;
    const int lane = tid & 31;
    const int wm = wid / NWN;
    const int wn = wid % NWN;
    const int row0 = blockIdx.y * TBM_;
    const int col0 = blockIdx.x * 128;
    const int nchunks = K / TBK;

    const int lr = lane & 7;
    const int j  = lane >> 3;
    const int arow  = ((j & 1) << 3) + lr;
    const int acsel = j >> 1;
    const int brow  = ((j >> 1) << 3) + lr;
    const int bcsel = j & 1;

    float acc[4][NJ][4];
#pragma unroll
    for (int mi = 0; mi < 4; mi++)
#pragma unroll
        for (int nj = 0; nj < NJ; nj++)
#pragma unroll
            for (int q = 0; q < 4; q++) acc[mi][nj][q] = 0.0f;

    auto load_chunk = [&](int stage, int k0) {
        uint32_t st = sb + stage * STAGE_;
#pragma unroll
        for (int i = 0; i < TBM_ / 32; i++) {
            int id = tid + i * 256;
            int r = id >> 3, c = id & 7;
            size_t off = (size_t)(row0 + r) * K + k0 + c * 8;
            cp16(st + swz(r, c), Ahi + off);
        }
#pragma unroll
        for (int i = 0; i < 4; i++) {
            int id = tid + i * 256;
            int r = id >> 3, c = id & 7;
            size_t off = (size_t)(col0 + r) * K + k0 + c * 8;
            cp16(st + A_TILE_ + swz(r, c), Bhi + off);
        }
    };

#pragma unroll
    for (int p = 0; p < NST - 1; p++) {
        load_chunk(p, p * TBK);
        CP_COMMIT();
    }

    for (int c = 0; c < nchunks; c++) {
        if (c == nchunks - 1) CP_WAIT(0); else CP_WAIT(NST - 2);
        __syncthreads();

        const int nxt = c + NST - 1;
        if (nxt < nchunks) {
            load_chunk(nxt % NST, nxt * TBK);
            CP_COMMIT();
        }

        const uint32_t sA = sb + (c % NST) * STAGE_;
        const uint32_t sB = sA + A_TILE_;

#pragma unroll
        for (int s = 0; s < 4; s++) {
            uint32_t ah[4][4], bh[PB][4];
#pragma unroll
            for (int mi = 0; mi < 4; mi++) {
                int r = wm * 64 + mi * 16 + arow;
                LDSM4(ah[mi], sA + swz(r, 2 * s + acsel));
            }
#pragma unroll
            for (int p = 0; p < PB; p++) {
                int r = wn * WNT + p * 16 + brow;
                LDSM4(bh[p], sB + swz(r, 2 * s + bcsel));
            }
#pragma unroll
            for (int mi = 0; mi < 4; mi++)
#pragma unroll
                for (int nj = 0; nj < NJ; nj++)
                    mma16816(acc[mi][nj], ah[mi], bh[nj >> 1][(nj & 1) * 2], bh[nj >> 1][(nj & 1) * 2 + 1]);
        }
    }

    // -------- epilogue --------
    const int g_ = lane >> 2, t = lane & 3;
    float psum[NJ][2];
    if (EPI == 2) {
#pragma unroll
        for (int nj = 0; nj < NJ; nj++) { psum[nj][0] = 0.0f; psum[nj][1] = 0.0f; }
    }
#pragma unroll
    for (int mi = 0; mi < 4; mi++) {
#pragma unroll
        for (int nj = 0; nj < NJ; nj++) {
            int row = row0 + wm * 64 + mi * 16 + g_;
            int col = col0 + wn * WNT + nj * 8 + 2 * t;
            size_t i0 = (size_t)row * N + col;
            size_t i1 = (size_t)(row + 8) * N + col;
            float* z = acc[mi][nj];
            if (EPI == 1) {
                float b0 = bias[col], b1 = bias[col + 1];
                *(__half2*)(Ohi + i0) = __floats2half2_rn(fmaxf(z[0] + b0, 0.f), fmaxf(z[1] + b1, 0.f));
                *(__half2*)(Ohi + i1) = __floats2half2_rn(fmaxf(z[2] + b0, 0.f), fmaxf(z[3] + b1, 0.f));
            } else if (EPI == 2) {
                float b0 = bias[col], b1 = bias[col + 1];
                float g0 = 1.0f / (1.0f + __expf(-(z[0] + b0)));
                float g1 = 1.0f / (1.0f + __expf(-(z[1] + b1)));
                float g2 = 1.0f / (1.0f + __expf(-(z[2] + b0)));
                float g3 = 1.0f / (1.0f + __expf(-(z[3] + b1)));
                float2 u0 = __half22float2(*(const __half2*)(uh + i0));
                float2 u1 = __half22float2(*(const __half2*)(uh + i1));
                float2 v0 = __half22float2(*(const __half2*)(vh + i0));
                float2 v1 = __half22float2(*(const __half2*)(vh + i1));
                __half2 ug0 = __floats2half2_rn(u0.x * g0, u0.y * g1);
                __half2 ug1 = __floats2half2_rn(u1.x * g2, u1.y * g3);
                *(__half2*)(ugb + i0) = ug0;
                *(__half2*)(ugb + i1) = ug1;
                *(__half2*)(vgb + i0) = __floats2half2_rn(v0.x * g0, v0.y * g1);
                *(__half2*)(vgb + i1) = __floats2half2_rn(v1.x * g2, v1.y * g3);
                float2 r0 = __half22float2(ug0), r1 = __half22float2(ug1);
                psum[nj][0] += r0.x + r1.x;
                psum[nj][1] += r0.y + r1.y;
            } else {  // EPI == 3: out = conv3(x) + z
                int l0 = row & (LL - 1);
                int l1 = l0 + 8;
                float w0a = cw[3 * col + 0], w1a = cw[3 * col + 1], w2a = cw[3 * col + 2];
                float w0b = cw[3 * col + 3], w1b = cw[3 * col + 4], w2b = cw[3 * col + 5];
                float cb0 = cb[col], cb1 = cb[col + 1];
                const float* xr0 = xp + i0;
                const float* xr1 = xp + i1;
                float2 xc0 = *(const float2*)xr0;
                float2 xc1 = *(const float2*)xr1;
                float2 xq0 = *(const float2*)(xr0 + N);
                float2 xm1 = *(const float2*)(xr1 - N);
                float2 xm0 = (l0 > 0)      ? *(const float2*)(xr0 - N) : make_float2(0.f, 0.f);
                float2 xq1 = (l1 < LL - 1) ? *(const float2*)(xr1 + N) : make_float2(0.f, 0.f);
                float o0 = cb0 + w1a * xc0.x + w2a * xq0.x + z[0] + (l0 > 0 ? w0a * xm0.x : 0.f);
                float o1 = cb1 + w1b * xc0.y + w2b * xq0.y + z[1] + (l0 > 0 ? w0b * xm0.y : 0.f);
                float o2 = cb0 + w1a * xc1.x + w0a * xm1.x + z[2] + (l1 < LL - 1 ? w2a * xq1.x : 0.f);
                float o3 = cb1 + w1b * xc1.y + w0b * xm1.y + z[3] + (l1 < LL - 1 ? w2b * xq1.y : 0.f);
                *(float2*)(C + i0) = make_float2(o0, o1);
                *(float2*)(C + i1) = make_float2(o2, o3);
            }
        }
    }

    if (EPI == 2) {
#pragma unroll
        for (int nj = 0; nj < NJ; nj++) {
#pragma unroll
            for (int k = 0; k < 2; k++) {
                float v = psum[nj][k];
                v += __shfl_xor_sync(0xffffffffu, v, 4);
                v += __shfl_xor_sync(0xffffffffu, v, 8);
                v += __shfl_xor_sync(0xffffffffu, v, 16);
                psum[nj][k] = v;
            }
        }
        __syncthreads();
        float* red = (float*)smem;
        if (lane < 4) {
#pragma unroll
            for (int nj = 0; nj < NJ; nj++) {
                red[wm * 128 + wn * WNT + nj * 8 + 2 * lane + 0] = psum[nj][0];
                red[wm * 128 + wn * WNT + nj * 8 + 2 * lane + 1] = psum[nj][1];
            }
        }
        __syncthreads();
        {
            int ch = tid >> 7, cl = tid & 127;
            if (ch < TBM_ / 128) {
                float s = red[(2 * ch) * 128 + cl] + red[(2 * ch + 1) * 128 + cl];
                int bidx = row0 >> 11;
                int cbase = (row0 & (LL - 1)) >> 7;
                part[((size_t)bidx * NCH + cbase + ch) * (size_t)N + col0 + cl] = s;
            }
        }
    }
}

// ---------------------------------------------------------------------------
// elementwise kernels
// ---------------------------------------------------------------------------
__device__ __forceinline__ uint32_t pack_h(float a, float b) {
    __half2 h = __halves2half2(__float2half(a), __float2half(b));
    return *(uint32_t*)&h;
}

__global__ void split_kernel(const float* __restrict__ s, __half* __restrict__ hi, size_t n) {
    size_t i = ((size_t)blockIdx.x * blockDim.x + threadIdx.x) * 8;
    if (i >= n) return;
    float4 a = *(const float4*)(s + i);
    float4 b = *(const float4*)(s + i + 4);
    uint4 h;
    h.x = pack_h(a.x, a.y); h.y = pack_h(a.z, a.w);
    h.z = pack_h(b.x, b.y); h.w = pack_h(b.z, b.w);
    *(uint4*)(hi + i) = h;
}

__global__ void scanB_kernel(float* __restrict__ part) {
    int tid = blockIdx.x * blockDim.x + threadIdx.x;
    if (tid >= BB * RR) return;
    int r = tid % RR;
    int b = tid / RR;
    float run = 0.0f;
    for (int c = 0; c < NCH; c++) {
        size_t idx = ((size_t)b * NCH + c) * RR + r;
        float t = part[idx];
        part[idx] = run;
        run += t;
    }
}

__global__ void scanC_kernel(const __half* __restrict__ ug, const __half* __restrict__ vg,
                             const float* __restrict__ part,
                             __half* __restrict__ ghi) {
    int tid = blockIdx.x * blockDim.x + threadIdx.x;
    if (tid >= BB * NCH * RR) return;
    int r = tid % RR;
    int c = (tid / RR) % NCH;
    int b = tid / (RR * NCH);
    float acc = part[((size_t)b * NCH + c) * RR + r];
    size_t base = ((size_t)b * LL + c * CHL) * RR + r;
    for (int l = 0; l < CHL; l++) {
        size_t idx = base + (size_t)l * RR;
        acc += __half2float(ug[idx]);
        ghi[idx] = __float2half(acc * __half2float(vg[idx]));
    }
}

// ---------------------------------------------------------------------------
extern "C" void kernel_launch(void* const* d_in, const int* in_sizes, int n_in,
                              void* d_out, int out_size) {
    const float* x      = (const float*)d_in[0];
    const float* Wu     = (const float*)d_in[1];
    const float* bu     = (const float*)d_in[2];
    const float* Wv     = (const float*)d_in[3];
    const float* bv     = (const float*)d_in[4];
    const float* Wg1    = (const float*)d_in[5];
    const float* bg1    = (const float*)d_in[6];
    const float* Wg2    = (const float*)d_in[7];
    const float* bg2    = (const float*)d_in[8];
    const float* conv_w = (const float*)d_in[9];
    const float* conv_b = (const float*)d_in[10];
    float* out = (float*)d_out;

    __half *xhi, *wuhi, *wvhi, *wg1hi, *wg2hi, *hhi, *ghi, *pu, *pv, *pug, *pvg;
    float *ppart;
    cudaGetSymbolAddress((void**)&xhi, g_xhi);
    cudaGetSymbolAddress((void**)&wuhi, g_wuhi);
    cudaGetSymbolAddress((void**)&wvhi, g_wvhi);
    cudaGetSymbolAddress((void**)&wg1hi, g_wg1hi);
    cudaGetSymbolAddress((void**)&wg2hi, g_wg2hi);
    cudaGetSymbolAddress((void**)&hhi, g_hhi);
    cudaGetSymbolAddress((void**)&ghi, g_ghi);
    cudaGetSymbolAddress((void**)&pu, g_u);        cudaGetSymbolAddress((void**)&pv, g_v);
    cudaGetSymbolAddress((void**)&pug, g_ug);      cudaGetSymbolAddress((void**)&pvg, g_vg);
    cudaGetSymbolAddress((void**)&ppart, g_part);

    cudaFuncSetAttribute(duogemm,          cudaFuncAttributeMaxDynamicSharedMemorySize, DUO_NST * DUO_STAGE);
    cudaFuncSetAttribute(bsgemm<1,2,1,2>,  cudaFuncAttributeMaxDynamicSharedMemorySize, 98304);
    cudaFuncSetAttribute(bsgemm<2,4,2,2>,  cudaFuncAttributeMaxDynamicSharedMemorySize, 65536);
    cudaFuncSetAttribute(bsgemm<3,4,2,3>,  cudaFuncAttributeMaxDynamicSharedMemorySize, 98304);

    // fp16 conversions
    split_kernel<<<(unsigned)((size_t)MM * DD / 8 / 256), 256>>>(x, xhi, (size_t)MM * DD);
    split_kernel<<<(unsigned)((size_t)RR * DD / 8 / 256), 256>>>(Wu, wuhi, (size_t)RR * DD);
    split_kernel<<<(unsigned)((size_t)RR * DD / 8 / 256), 256>>>(Wv, wvhi, (size_t)RR * DD);

    // dual-output u/v GEMM: A loaded once per stage, TBK=128 (16 barriers)
    duogemm<<<dim3(RR / 128, MM / 128), 256, DUO_NST * DUO_STAGE>>>(
        xhi, wuhi, wvhi, bu, bv, pu, pv, MM, RR, DD);

    // gate path (plain fp16)
    split_kernel<<<(unsigned)((size_t)DHH * DD / 8 / 256), 256>>>(Wg1, wg1hi, (size_t)DHH * DD);
    split_kernel<<<(unsigned)((size_t)RR * DHH / 8 / 256), 256>>>(Wg2, wg2hi, (size_t)RR * DHH);
    // h = relu(x Wg1^T + bg1) -> fp16
    bsgemm<1,2,1,2><<<dim3(DHH / 128, MM / 256), 256, 98304>>>(
        xhi, wg1hi, bg1, nullptr, hhi,
        nullptr, nullptr, nullptr, nullptr,
        nullptr, nullptr, nullptr, nullptr, MM, DHH, DD);
    // gates: compute g, write ug/vg fp16, chunk partial sums of ug -> part
    bsgemm<2,4,2,2><<<dim3(RR / 128, MM / 128), 256, 65536>>>(
        hhi, wg2hi, bg2, nullptr, nullptr,
        pu, pv, pug, pvg,
        nullptr, nullptr, nullptr, ppart, MM, RR, DHH);

    // exclusive prefix over chunks, then cumsum + multiply -> fp16
    scanB_kernel<<<(BB * RR + 255) / 256, 256>>>(ppart);
    scanC_kernel<<<(BB * NCH * RR + 255) / 256, 256>>>(pug, pvg, ppart, ghi);

    // out = conv3(x) + global_out @ Wu
    bsgemm<3,4,2,3><<<dim3(DD / 128, MM / 128), 256, 98304>>>(
        ghi, wuhi, nullptr, out, nullptr,
        nullptr, nullptr, nullptr, nullptr,
        conv_w, conv_b, x, nullptr, MM, DD, RR);
}